// round 7
// baseline (speedup 1.0000x reference)
#include <cuda_runtime.h>
#include <cstdint>

// Problem constants (fixed shapes for this problem)
#define TT   128
#define NN   50000
#define EE   1600000
#define CIN  16
#define CH   32
#define COUTC 8
#define SROW 36            // padded smem row stride (floats): 16B-aligned, +4 banks
#define FULL 0xFFFFFFFFu

#define GETC(v,u) ((u)==0?(v).x:(u)==1?(v).y:(u)==2?(v).z:(v).w)

// ---------------- scratch (device globals; no runtime allocation) ----------
__device__ int   g_is64;
__device__ int   g_cnt_src[NN];
__device__ int   g_cnt_dst[NN];
__device__ int   g_cursor[NN];
__device__ int   g_off[NN + 1];
__device__ float g_dinv[NN];
__device__ __align__(16) int2  g_csr[EE];          // {src, w-bits}
__device__ __align__(16) float g_h[NN * CH];
__device__ __align__(16) float g_hR[NN * CH];
__device__ float g_Z[NN * CH];
__device__ float g_AX[(size_t)TT * NN * CIN];      // agg(x_t) for all t

// ---------------- preprocessing (single block) ----------------
// detect dtype + zero state + degree count + dinv + exclusive scan.
// One block of 1024 threads; one-time ~0.4ms. Keeps k_gru_a at launch idx 3.
__global__ void __launch_bounds__(1024) k_prep(const void* __restrict__ ei, int E) {
    __shared__ int s[1024];
    __shared__ int carry_s;
    int tid = threadIdx.x;

    // ---- dtype detect ----
    long long v = ((const long long*)ei)[tid];
    int bad = (v < 0 || v >= NN) ? 1 : 0;
    int anybad = __syncthreads_or(bad);
    int is64 = anybad ? 0 : 1;
    if (tid == 0) g_is64 = is64;

    // ---- zero h + counters ----
    float4 z4 = make_float4(0.f, 0.f, 0.f, 0.f);
    for (int i = tid; i < NN * CH / 4; i += 1024) ((float4*)g_h)[i] = z4;
    for (int i = tid; i < NN; i += 1024) {
        g_cnt_src[i] = 0; g_cnt_dst[i] = 0; g_cursor[i] = 0;
    }
    __syncthreads();

    // ---- degree count ----
    if (is64) {
        const long long* e64 = (const long long*)ei;
        for (int i = tid; i < E; i += 1024) {
            long long sl = e64[i], dl = e64[(size_t)E + i];
            if (sl >= 0 && sl < NN) atomicAdd(&g_cnt_src[(int)sl], 1);
            if (dl >= 0 && dl < NN) atomicAdd(&g_cnt_dst[(int)dl], 1);
        }
    } else {
        const int* e32 = (const int*)ei;
        for (int i = tid; i < E; i += 1024) {
            int sl = e32[i], dl = e32[E + i];
            if (sl >= 0 && sl < NN) atomicAdd(&g_cnt_src[sl], 1);
            if (dl >= 0 && dl < NN) atomicAdd(&g_cnt_dst[dl], 1);
        }
    }
    __threadfence();
    __syncthreads();

    // ---- dinv ----
    for (int n = tid; n < NN; n += 1024) {
        int dsrc = g_cnt_src[n];
        g_dinv[n] = (dsrc > 0) ? rsqrtf((float)dsrc) : 0.f;
    }
    __syncthreads();

    // ---- exclusive scan of cnt_dst -> g_off ----
    if (tid == 0) carry_s = 0;
    __syncthreads();
    for (int base = 0; base < NN; base += 1024) {
        int i = base + tid;
        int val = (i < NN) ? g_cnt_dst[i] : 0;
        s[tid] = val;
        __syncthreads();
        for (int off = 1; off < 1024; off <<= 1) {
            int x = (tid >= off) ? s[tid - off] : 0;
            __syncthreads();
            s[tid] += x;
            __syncthreads();
        }
        if (i < NN) g_off[i] = carry_s + s[tid] - val;
        __syncthreads();
        if (tid == 0) carry_s += s[1023];
        __syncthreads();
    }
    if (tid == 0) g_off[NN] = carry_s;
}

// launch 1: fill CSR (grid-wide)
__global__ void k_fill(const void* __restrict__ ei, int E) {
    int i = blockIdx.x * blockDim.x + threadIdx.x;
    if (i >= E) return;
    long long sl, dl;
    if (g_is64) {
        sl = ((const long long*)ei)[i];
        dl = ((const long long*)ei)[(size_t)E + i];
    } else {
        sl = ((const int*)ei)[i];
        dl = ((const int*)ei)[E + i];
    }
    if (sl < 0 || sl >= NN || dl < 0 || dl >= NN) return;
    int s = (int)sl, d = (int)dl;
    int pos = g_off[d] + atomicAdd(&g_cursor[d], 1);
    g_csr[pos] = make_int2(s, __float_as_int(-g_dinv[s] * g_dinv[d]));
}

// ---------------- gather helper: warp-uniform int4 CSR reads, MLP=4 -------
__device__ __forceinline__ float gather_h(const float* __restrict__ src, int n, int lane) {
    int i = g_off[n], end = g_off[n + 1];
    float a0 = 0.f, a1 = 0.f, a2 = 0.f, a3 = 0.f;
    if (i < end && (i & 1)) {          // align to int4 boundary
        int2 e = g_csr[i];
        a0 += __int_as_float(e.y) * src[e.x * CH + lane];
        i++;
    }
    for (; i + 4 <= end; i += 4) {
        int4 e01 = *(const int4*)&g_csr[i];
        int4 e23 = *(const int4*)&g_csr[i + 2];
        a0 += __int_as_float(e01.y) * src[e01.x * CH + lane];
        a1 += __int_as_float(e01.w) * src[e01.z * CH + lane];
        a2 += __int_as_float(e23.y) * src[e23.x * CH + lane];
        a3 += __int_as_float(e23.w) * src[e23.z * CH + lane];
    }
    for (; i < end; i++) {
        int2 e = g_csr[i];
        a0 += __int_as_float(e.y) * src[e.x * CH + lane];
    }
    return (a0 + a1) + (a2 + a3);
}

// ---------------- time-parallel precompute: AX[t,n,:] = agg(x_t)[n] -------
// 8 warps/block; warp = node, half-warps = two timesteps, ch = lane&15.
__global__ void __launch_bounds__(256, 4) k_ax(const float* __restrict__ X) {
    int warp = threadIdx.x >> 5, lane = threadIdx.x & 31;
    int tp = blockIdx.x / (NN / 8);
    int nb = blockIdx.x % (NN / 8);
    int n  = nb * 8 + warp;
    int t  = tp * 2 + (lane >> 4);
    int ch = lane & 15;
    const float* Xt = X + (size_t)t * NN * CIN;

    int i = g_off[n], end = g_off[n + 1];
    float a0 = 0.f, a1 = 0.f, a2 = 0.f, a3 = 0.f;
    if (i < end && (i & 1)) {
        int2 e = g_csr[i];
        a0 += __int_as_float(e.y) * Xt[e.x * CIN + ch];
        i++;
    }
    for (; i + 4 <= end; i += 4) {
        int4 e01 = *(const int4*)&g_csr[i];
        int4 e23 = *(const int4*)&g_csr[i + 2];
        a0 += __int_as_float(e01.y) * Xt[e01.x * CIN + ch];
        a1 += __int_as_float(e01.w) * Xt[e01.z * CIN + ch];
        a2 += __int_as_float(e23.y) * Xt[e23.x * CIN + ch];
        a3 += __int_as_float(e23.w) * Xt[e23.z * CIN + ch];
    }
    for (; i < end; i++) {
        int2 e = g_csr[i];
        a0 += __int_as_float(e.y) * Xt[e.x * CIN + ch];
    }
    g_AX[((size_t)t * NN + n) * CIN + ch] = (a0 + a1) + (a2 + a3);
}

// ---------------- recurrence kernels ----------------
// 256 thr = 8 warps/block. Warp handles FOUR consecutive nodes (amortizes the
// per-lane-distinct weight LDS.128 across 16 FFMAs). Lane = hidden channel.

__global__ void __launch_bounds__(256, 3) k_gru_a(
    int t, const float* __restrict__ X,
    const float* __restrict__ Wxz, const float* __restrict__ bxz,
    const float* __restrict__ Whz, const float* __restrict__ bhz,
    const float* __restrict__ Wxr, const float* __restrict__ bxr,
    const float* __restrict__ Whr, const float* __restrict__ bhr)
{
    __shared__ float4 s_wx[CIN * CH];   // {wxz0, wxz1, wxr0, wxr1}[c][j]
    __shared__ float4 s_wh[CH * CH];    // {whz0, whz1, whr0, whr1}[c][j]
    __shared__ float  s_bz[CH], s_br[CH];
    // slots: 0..7 = h0,a0,h1,a1,h2,a2,h3,a3 ; 8..11 = xp0..xp3
    __shared__ __align__(16) float s_st[8][12][SROW];
    int tid = threadIdx.x;
    for (int i = tid; i < CIN * CH; i += 256)
        s_wx[i] = make_float4(Wxz[i], Wxz[CIN * CH + i], Wxr[i], Wxr[CIN * CH + i]);
    for (int i = tid; i < CH * CH; i += 256)
        s_wh[i] = make_float4(Whz[i], Whz[CH * CH + i], Whr[i], Whr[CH * CH + i]);
    if (tid < CH) { s_bz[tid] = bxz[tid] + bhz[tid]; s_br[tid] = bxr[tid] + bhr[tid]; }
    __syncthreads();

    const float* Xt  = X + (size_t)t * NN * CIN;
    const float* AXt = g_AX + (size_t)t * NN * CIN;
    int lane = tid & 31, wid = tid >> 5;
    int cx = lane & 15;
    int gw = blockIdx.x * 8 + wid, nw = gridDim.x * 8;
    for (int p = gw; p < NN / 4; p += nw) {
        int n0 = 4 * p;
        float h0 = g_h[(n0 + 0) * CH + lane];
        float h1 = g_h[(n0 + 1) * CH + lane];
        float h2 = g_h[(n0 + 2) * CH + lane];
        float h3 = g_h[(n0 + 3) * CH + lane];
        // packed x vectors: [0..15]=x, [16..31]=agg(x)
        float xp0, xp1, xp2, xp3;
        if (lane < 16) {
            xp0 = Xt[(n0 + 0) * CIN + cx];  xp1 = Xt[(n0 + 1) * CIN + cx];
            xp2 = Xt[(n0 + 2) * CIN + cx];  xp3 = Xt[(n0 + 3) * CIN + cx];
        } else {
            xp0 = AXt[(n0 + 0) * CIN + cx]; xp1 = AXt[(n0 + 1) * CIN + cx];
            xp2 = AXt[(n0 + 2) * CIN + cx]; xp3 = AXt[(n0 + 3) * CIN + cx];
        }
        float a0 = gather_h(g_h, n0 + 0, lane);
        float a1 = gather_h(g_h, n0 + 1, lane);
        float a2 = gather_h(g_h, n0 + 2, lane);
        float a3 = gather_h(g_h, n0 + 3, lane);

        s_st[wid][0][lane] = h0;  s_st[wid][1][lane] = a0;
        s_st[wid][2][lane] = h1;  s_st[wid][3][lane] = a1;
        s_st[wid][4][lane] = h2;  s_st[wid][5][lane] = a2;
        s_st[wid][6][lane] = h3;  s_st[wid][7][lane] = a3;
        s_st[wid][8][lane] = xp0; s_st[wid][9][lane] = xp1;
        s_st[wid][10][lane] = xp2; s_st[wid][11][lane] = xp3;
        __syncwarp();

        float z0 = s_bz[lane], r0 = s_br[lane];
        float z1 = z0, r1 = r0, z2 = z0, r2 = r0, z3 = z0, r3 = r0;

        // x side: c in 0..15 ; x quad = [c4], agg(x) quad = [4+c4]
#pragma unroll
        for (int c4 = 0; c4 < 4; c4++) {
            float4 x0q = ((const float4*)&s_st[wid][8][0])[c4];
            float4 A0q = ((const float4*)&s_st[wid][8][0])[4 + c4];
            float4 x1q = ((const float4*)&s_st[wid][9][0])[c4];
            float4 A1q = ((const float4*)&s_st[wid][9][0])[4 + c4];
            float4 x2q = ((const float4*)&s_st[wid][10][0])[c4];
            float4 A2q = ((const float4*)&s_st[wid][10][0])[4 + c4];
            float4 x3q = ((const float4*)&s_st[wid][11][0])[c4];
            float4 A3q = ((const float4*)&s_st[wid][11][0])[4 + c4];
#pragma unroll
            for (int u = 0; u < 4; u++) {
                float4 w = s_wx[(c4 * 4 + u) * CH + lane];
                float xa, aa;
                xa = GETC(x0q, u); aa = GETC(A0q, u);
                z0 += xa * w.x + aa * w.y;  r0 += xa * w.z + aa * w.w;
                xa = GETC(x1q, u); aa = GETC(A1q, u);
                z1 += xa * w.x + aa * w.y;  r1 += xa * w.z + aa * w.w;
                xa = GETC(x2q, u); aa = GETC(A2q, u);
                z2 += xa * w.x + aa * w.y;  r2 += xa * w.z + aa * w.w;
                xa = GETC(x3q, u); aa = GETC(A3q, u);
                z3 += xa * w.x + aa * w.y;  r3 += xa * w.z + aa * w.w;
            }
        }
        // h side: c in 0..31
#pragma unroll
        for (int c4 = 0; c4 < 8; c4++) {
            float4 h0q = ((const float4*)&s_st[wid][0][0])[c4];
            float4 a0q = ((const float4*)&s_st[wid][1][0])[c4];
            float4 h1q = ((const float4*)&s_st[wid][2][0])[c4];
            float4 a1q = ((const float4*)&s_st[wid][3][0])[c4];
            float4 h2q = ((const float4*)&s_st[wid][4][0])[c4];
            float4 a2q = ((const float4*)&s_st[wid][5][0])[c4];
            float4 h3q = ((const float4*)&s_st[wid][6][0])[c4];
            float4 a3q = ((const float4*)&s_st[wid][7][0])[c4];
#pragma unroll
            for (int u = 0; u < 4; u++) {
                float4 w = s_wh[(c4 * 4 + u) * CH + lane];
                float ha, aa;
                ha = GETC(h0q, u); aa = GETC(a0q, u);
                z0 += ha * w.x + aa * w.y;  r0 += ha * w.z + aa * w.w;
                ha = GETC(h1q, u); aa = GETC(a1q, u);
                z1 += ha * w.x + aa * w.y;  r1 += ha * w.z + aa * w.w;
                ha = GETC(h2q, u); aa = GETC(a2q, u);
                z2 += ha * w.x + aa * w.y;  r2 += ha * w.z + aa * w.w;
                ha = GETC(h3q, u); aa = GETC(a3q, u);
                z3 += ha * w.x + aa * w.y;  r3 += ha * w.z + aa * w.w;
            }
        }
        z0 = 1.f / (1.f + __expf(-z0));  r0 = 1.f / (1.f + __expf(-r0));
        z1 = 1.f / (1.f + __expf(-z1));  r1 = 1.f / (1.f + __expf(-r1));
        z2 = 1.f / (1.f + __expf(-z2));  r2 = 1.f / (1.f + __expf(-r2));
        z3 = 1.f / (1.f + __expf(-z3));  r3 = 1.f / (1.f + __expf(-r3));
        g_Z [(n0 + 0) * CH + lane] = z0;  g_hR[(n0 + 0) * CH + lane] = h0 * r0;
        g_Z [(n0 + 1) * CH + lane] = z1;  g_hR[(n0 + 1) * CH + lane] = h1 * r1;
        g_Z [(n0 + 2) * CH + lane] = z2;  g_hR[(n0 + 2) * CH + lane] = h2 * r2;
        g_Z [(n0 + 3) * CH + lane] = z3;  g_hR[(n0 + 3) * CH + lane] = h3 * r3;
        __syncwarp();
    }
}

__global__ void __launch_bounds__(256, 3) k_gru_b(
    int t, const float* __restrict__ X,
    const float* __restrict__ Wxh, const float* __restrict__ bxh,
    const float* __restrict__ Whh, const float* __restrict__ bhh,
    const float* __restrict__ fcw, const float* __restrict__ fcb,
    float* __restrict__ out)
{
    __shared__ float2 s_wx[CIN * CH];   // {wxh0, wxh1}
    __shared__ float2 s_wh[CH * CH];    // {whh0, whh1}
    __shared__ float  s_fcw[CH * COUTC];
    __shared__ float  s_bh[CH];
    __shared__ float  s_fcb[COUTC];
    // slots: 0..7 = hr0,a0,...,hr3,a3 ; 8..11 = xp ; 12..15 = hn
    __shared__ __align__(16) float s_st[8][16][SROW];
    int tid = threadIdx.x;
    for (int i = tid; i < CIN * CH; i += 256)
        s_wx[i] = make_float2(Wxh[i], Wxh[CIN * CH + i]);
    for (int i = tid; i < CH * CH; i += 256)
        s_wh[i] = make_float2(Whh[i], Whh[CH * CH + i]);
    for (int i = tid; i < CH * COUTC; i += 256) s_fcw[i] = fcw[i];
    if (tid < CH)    s_bh[tid]  = bxh[tid] + bhh[tid];
    if (tid < COUTC) s_fcb[tid] = fcb[tid];
    __syncthreads();

    const float* Xt  = X + (size_t)t * NN * CIN;
    const float* AXt = g_AX + (size_t)t * NN * CIN;
    int lane = tid & 31, wid = tid >> 5;
    int cx = lane & 15;
    int gw = blockIdx.x * 8 + wid, nw = gridDim.x * 8;
    for (int p = gw; p < NN / 4; p += nw) {
        int n0 = 4 * p;
        float h0 = g_h[(n0 + 0) * CH + lane];
        float h1 = g_h[(n0 + 1) * CH + lane];
        float h2 = g_h[(n0 + 2) * CH + lane];
        float h3 = g_h[(n0 + 3) * CH + lane];
        float hr0 = g_hR[(n0 + 0) * CH + lane];
        float hr1 = g_hR[(n0 + 1) * CH + lane];
        float hr2 = g_hR[(n0 + 2) * CH + lane];
        float hr3 = g_hR[(n0 + 3) * CH + lane];
        float zz0 = g_Z[(n0 + 0) * CH + lane];
        float zz1 = g_Z[(n0 + 1) * CH + lane];
        float zz2 = g_Z[(n0 + 2) * CH + lane];
        float zz3 = g_Z[(n0 + 3) * CH + lane];
        float xp0, xp1, xp2, xp3;
        if (lane < 16) {
            xp0 = Xt[(n0 + 0) * CIN + cx];  xp1 = Xt[(n0 + 1) * CIN + cx];
            xp2 = Xt[(n0 + 2) * CIN + cx];  xp3 = Xt[(n0 + 3) * CIN + cx];
        } else {
            xp0 = AXt[(n0 + 0) * CIN + cx]; xp1 = AXt[(n0 + 1) * CIN + cx];
            xp2 = AXt[(n0 + 2) * CIN + cx]; xp3 = AXt[(n0 + 3) * CIN + cx];
        }
        float a0 = gather_h(g_hR, n0 + 0, lane);
        float a1 = gather_h(g_hR, n0 + 1, lane);
        float a2 = gather_h(g_hR, n0 + 2, lane);
        float a3 = gather_h(g_hR, n0 + 3, lane);

        s_st[wid][0][lane] = hr0; s_st[wid][1][lane] = a0;
        s_st[wid][2][lane] = hr1; s_st[wid][3][lane] = a1;
        s_st[wid][4][lane] = hr2; s_st[wid][5][lane] = a2;
        s_st[wid][6][lane] = hr3; s_st[wid][7][lane] = a3;
        s_st[wid][8][lane] = xp0; s_st[wid][9][lane] = xp1;
        s_st[wid][10][lane] = xp2; s_st[wid][11][lane] = xp3;
        __syncwarp();

        float c0 = s_bh[lane], c1 = c0, c2 = c0, c3 = c0;

#pragma unroll
        for (int c4 = 0; c4 < 4; c4++) {
            float4 x0q = ((const float4*)&s_st[wid][8][0])[c4];
            float4 A0q = ((const float4*)&s_st[wid][8][0])[4 + c4];
            float4 x1q = ((const float4*)&s_st[wid][9][0])[c4];
            float4 A1q = ((const float4*)&s_st[wid][9][0])[4 + c4];
            float4 x2q = ((const float4*)&s_st[wid][10][0])[c4];
            float4 A2q = ((const float4*)&s_st[wid][10][0])[4 + c4];
            float4 x3q = ((const float4*)&s_st[wid][11][0])[c4];
            float4 A3q = ((const float4*)&s_st[wid][11][0])[4 + c4];
#pragma unroll
            for (int u = 0; u < 4; u++) {
                float2 w = s_wx[(c4 * 4 + u) * CH + lane];
                c0 += GETC(x0q, u) * w.x + GETC(A0q, u) * w.y;
                c1 += GETC(x1q, u) * w.x + GETC(A1q, u) * w.y;
                c2 += GETC(x2q, u) * w.x + GETC(A2q, u) * w.y;
                c3 += GETC(x3q, u) * w.x + GETC(A3q, u) * w.y;
            }
        }
#pragma unroll
        for (int c4 = 0; c4 < 8; c4++) {
            float4 h0q = ((const float4*)&s_st[wid][0][0])[c4];
            float4 a0q = ((const float4*)&s_st[wid][1][0])[c4];
            float4 h1q = ((const float4*)&s_st[wid][2][0])[c4];
            float4 a1q = ((const float4*)&s_st[wid][3][0])[c4];
            float4 h2q = ((const float4*)&s_st[wid][4][0])[c4];
            float4 a2q = ((const float4*)&s_st[wid][5][0])[c4];
            float4 h3q = ((const float4*)&s_st[wid][6][0])[c4];
            float4 a3q = ((const float4*)&s_st[wid][7][0])[c4];
#pragma unroll
            for (int u = 0; u < 4; u++) {
                float2 w = s_wh[(c4 * 4 + u) * CH + lane];
                c0 += GETC(h0q, u) * w.x + GETC(a0q, u) * w.y;
                c1 += GETC(h1q, u) * w.x + GETC(a1q, u) * w.y;
                c2 += GETC(h2q, u) * w.x + GETC(a2q, u) * w.y;
                c3 += GETC(h3q, u) * w.x + GETC(a3q, u) * w.y;
            }
        }
        float hn0 = zz0 * h0 + (1.f - zz0) * tanhf(c0);
        float hn1 = zz1 * h1 + (1.f - zz1) * tanhf(c1);
        float hn2 = zz2 * h2 + (1.f - zz2) * tanhf(c2);
        float hn3 = zz3 * h3 + (1.f - zz3) * tanhf(c3);
        g_h[(n0 + 0) * CH + lane] = hn0;
        g_h[(n0 + 1) * CH + lane] = hn1;
        g_h[(n0 + 2) * CH + lane] = hn2;
        g_h[(n0 + 3) * CH + lane] = hn3;

        // out[t, n0..n0+3, :] = hn @ fc_w + fc_b
        // lane -> (node = lane>>3, j = lane&7): one fully-coalesced 128B STG
        s_st[wid][12][lane] = hn0;
        s_st[wid][13][lane] = hn1;
        s_st[wid][14][lane] = hn2;
        s_st[wid][15][lane] = hn3;
        __syncwarp();
        {
            int node = lane >> 3, j = lane & 7;
            const float* hn = &s_st[wid][12 + node][0];
            float acc = s_fcb[j];
#pragma unroll
            for (int c = 0; c < CH; c++) acc += hn[c] * s_fcw[c * COUTC + j];
            out[((size_t)t * NN + n0) * COUTC + lane] = acc;
        }
        __syncwarp();
    }
}

// ---------------- launch ----------------
extern "C" void kernel_launch(void* const* d_in, const int* in_sizes, int n_in,
                              void* d_out, int out_size) {
    const float* X   = (const float*)d_in[0];
    const void*  ei  = d_in[1];
    const float* Wxz = (const float*)d_in[2];
    const float* bxz = (const float*)d_in[3];
    const float* Whz = (const float*)d_in[4];
    const float* bhz = (const float*)d_in[5];
    const float* Wxr = (const float*)d_in[6];
    const float* bxr = (const float*)d_in[7];
    const float* Whr = (const float*)d_in[8];
    const float* bhr = (const float*)d_in[9];
    const float* Wxh = (const float*)d_in[10];
    const float* bxh = (const float*)d_in[11];
    const float* Whh = (const float*)d_in[12];
    const float* bhh = (const float*)d_in[13];
    const float* fcw = (const float*)d_in[14];
    const float* fcb = (const float*)d_in[15];
    float* out = (float*)d_out;

    int E = in_sizes[1] / 2;

    // preprocess: prep(0), fill(1), ax(2) -> first k_gru_a is launch idx 3 (ncu)
    k_prep<<<1, 1024>>>(ei, E);
    k_fill<<<(E + 255) / 256, 256>>>(ei, E);
    k_ax<<<(TT / 2) * (NN / 8), 256>>>(X);

    // sequential GRU recurrence
    for (int t = 0; t < TT; t++) {
        k_gru_a<<<444, 256>>>(t, X, Wxz, bxz, Whz, bhz, Wxr, bxr, Whr, bhr);
        k_gru_b<<<444, 256>>>(t, X, Wxh, bxh, Whh, bhh, fcw, fcb, out);
    }
}